// round 13
// baseline (speedup 1.0000x reference)
#include <cuda_runtime.h>

// LIF neuron scan, round 12: r9 geometry (bench-best) + 2 barriers/iter +
// shortened recurrence critical path.
//
// r9/r10/r11 all pin DRAM ~72% (HBM mixed r/w ceiling); remaining cost is
// per-iteration critical-path cycles. Changes vs r9:
//  1. Barrier order: cp_wait<0> -> bulk_wait<1> -> ONE sync -> prefetch issue.
//     With distance-1 prefetch only one load group is outstanding at iter
//     top, so wait<0> == "my tile landed"; drops a barrier pair (3->2).
//  2. LIF step: compute u=fma(v,.5,x) and u-0.5 in parallel, resolve with
//     FSEL off the FSETP predicate. Chain 16 -> 12 cyc/step (1600->1200/row).

#define T_STEPS   100
#define T_VEC     (T_STEPS / 4)        // 25 float4 per row
#define ROWS_CTA  128
#define TILE_V4   (ROWS_CTA * T_VEC)   // 3200 float4 = 50 KB
#define TILE_BYTES (TILE_V4 * 16)
#define GRID_P    148                  // 1 persistent CTA per SM

__device__ __forceinline__ void cp_async16(float4* smem_dst, const float4* gmem_src) {
    unsigned saddr = (unsigned)__cvta_generic_to_shared(smem_dst);
    asm volatile("cp.async.cg.shared.global [%0], [%1], 16;\n" :: "r"(saddr), "l"(gmem_src));
}
__device__ __forceinline__ void cp_commit() {
    asm volatile("cp.async.commit_group;\n");
}
template <int N>
__device__ __forceinline__ void cp_wait() {
    asm volatile("cp.async.wait_group %0;\n" :: "n"(N));
}

__device__ __forceinline__ void bulk_store(float4* gmem_dst, const float4* smem_src, unsigned bytes) {
    unsigned saddr = (unsigned)__cvta_generic_to_shared(smem_src);
    asm volatile("cp.async.bulk.global.shared::cta.bulk_group [%0], [%1], %2;\n"
                 :: "l"(gmem_dst), "r"(saddr), "r"(bytes) : "memory");
}
__device__ __forceinline__ void bulk_commit() {
    asm volatile("cp.async.bulk.commit_group;\n");
}
template <int N>
__device__ __forceinline__ void bulk_wait() {
    asm volatile("cp.async.bulk.wait_group %0;\n" :: "n"(N) : "memory");
}
__device__ __forceinline__ void fence_async_proxy() {
    asm volatile("fence.proxy.async.shared::cta;\n" ::: "memory");
}

// One LIF timestep, 12-cycle critical path:
//   u = fma(v, 0.5, x); um = u - 0.5 (parallel with setp); v = sp ? um : u.
__device__ __forceinline__ void lif_step(float& v, float x, float& s_out) {
    float u  = fmaf(v, 0.5f, x);
    float um = u - 0.5f;
    bool  sp = u > 0.5f;
    s_out = sp ? 1.0f : 0.0f;   // off critical path
    v     = sp ? um : u;        // FSEL, pred-as-data
}

__global__ __launch_bounds__(ROWS_CTA, 1) void lif_kernel(const float4* __restrict__ x,
                                                          float4* __restrict__ out,
                                                          int ntiles) {
    extern __shared__ float4 smem[];              // [3 * TILE_V4]
    float4* bufs[3] = { smem, smem + TILE_V4, smem + 2 * TILE_V4 };

    const int tid    = threadIdx.x;
    const int stride = gridDim.x;

    const int tile0 = blockIdx.x;
    if (tile0 >= ntiles) return;

    // Prologue: prefetch first tile into buffer 0 (one load group in flight).
    {
        const float4* src = x + (long long)tile0 * TILE_V4;
        float4* dst = bufs[0];
        #pragma unroll
        for (int i = 0; i < T_VEC; ++i)
            cp_async16(&dst[tid + ROWS_CTA * i], &src[tid + ROWS_CTA * i]);
        cp_commit();
    }

    int j = 0;
    for (long long tile = tile0; tile < ntiles; tile += stride, ++j) {
        float4* cur = bufs[j % 3];
        float4* nxt = bufs[(j + 1) % 3];

        // 1. My tile landed (only group outstanding at iter top).
        cp_wait<0>();
        // 2. Free the prefetch target: its store (iter j-2) is the oldest of
        //    at most 2 outstanding bulk stores.
        if (tid == 0) bulk_wait<1>();
        __syncthreads();

        // 3. Fire next tile's load into nxt (overlaps compute+store below).
        long long next = tile + stride;
        if (next < ntiles) {
            const float4* src = x + next * TILE_V4;
            #pragma unroll
            for (int i = 0; i < T_VEC; ++i)
                cp_async16(&nxt[tid + ROWS_CTA * i], &src[tid + ROWS_CTA * i]);
            cp_commit();
        }

        // 4. Compute: serial LIF scan of this thread's row, in place.
        float v = 0.0f;
        float4* __restrict__ row = cur + tid * T_VEC;

        #pragma unroll
        for (int i = 0; i < T_VEC; ++i) {
            float4 xi = row[i];
            float4 so;
            lif_step(v, xi.x, so.x);
            lif_step(v, xi.y, so.y);
            lif_step(v, xi.z, so.z);
            lif_step(v, xi.w, so.w);
            row[i] = so;
        }

        // 5. Order generic smem writes before async-proxy read, then
        //    fire-and-forget the 50 KB tile store.
        fence_async_proxy();
        __syncthreads();
        if (tid == 0) {
            bulk_store(out + tile * TILE_V4, cur, TILE_BYTES);
            bulk_commit();
        }
    }

    // Drain outstanding bulk stores before exit.
    if (tid == 0) bulk_wait<0>();
}

extern "C" void kernel_launch(void* const* d_in, const int* in_sizes, int n_in,
                              void* d_out, int out_size) {
    const float4* x = (const float4*)d_in[0];
    float4* out = (float4*)d_out;

    int n_rows = in_sizes[0] / T_STEPS;          // 524288
    int ntiles = n_rows / ROWS_CTA;              // 4096

    size_t smem_bytes = 3 * (size_t)TILE_V4 * sizeof(float4);   // 150 KB
    static bool attr_set = false;
    if (!attr_set) {
        cudaFuncSetAttribute(lif_kernel, cudaFuncAttributeMaxDynamicSharedMemorySize,
                             (int)smem_bytes);
        attr_set = true;
    }
    int grid = ntiles < GRID_P ? ntiles : GRID_P;
    lif_kernel<<<grid, ROWS_CTA, smem_bytes>>>(x, out, ntiles);
}

// round 14
// speedup vs baseline: 1.1424x; 1.1424x over previous
#include <cuda_runtime.h>

// LIF neuron scan, round 13: revert to r9 pipeline ordering (bench-best),
// keep the shortened LIF step from r12.
//
// r12 lesson: moving cp_wait to the top of the iteration (before issuing the
// next prefetch) drains the read stream every iteration -> DRAM 72%->58%,
// 62->78 us. The r9 order -- ISSUE next load first, THEN wait for current --
// keeps the LSU queue non-empty across the stall and is what sustained 72%.
// Kept from r12: lif_step with parallel u/um and FSEL resolve (12-cyc chain).

#define T_STEPS   100
#define T_VEC     (T_STEPS / 4)        // 25 float4 per row
#define ROWS_CTA  128
#define TILE_V4   (ROWS_CTA * T_VEC)   // 3200 float4 = 50 KB
#define TILE_BYTES (TILE_V4 * 16)
#define GRID_P    148                  // 1 persistent CTA per SM

__device__ __forceinline__ void cp_async16(float4* smem_dst, const float4* gmem_src) {
    unsigned saddr = (unsigned)__cvta_generic_to_shared(smem_dst);
    asm volatile("cp.async.cg.shared.global [%0], [%1], 16;\n" :: "r"(saddr), "l"(gmem_src));
}
__device__ __forceinline__ void cp_commit() {
    asm volatile("cp.async.commit_group;\n");
}
template <int N>
__device__ __forceinline__ void cp_wait() {
    asm volatile("cp.async.wait_group %0;\n" :: "n"(N));
}

__device__ __forceinline__ void bulk_store(float4* gmem_dst, const float4* smem_src, unsigned bytes) {
    unsigned saddr = (unsigned)__cvta_generic_to_shared(smem_src);
    asm volatile("cp.async.bulk.global.shared::cta.bulk_group [%0], [%1], %2;\n"
                 :: "l"(gmem_dst), "r"(saddr), "r"(bytes) : "memory");
}
__device__ __forceinline__ void bulk_commit() {
    asm volatile("cp.async.bulk.commit_group;\n");
}
template <int N>
__device__ __forceinline__ void bulk_wait() {
    asm volatile("cp.async.bulk.wait_group %0;\n" :: "n"(N) : "memory");
}
__device__ __forceinline__ void fence_async_proxy() {
    asm volatile("fence.proxy.async.shared::cta;\n" ::: "memory");
}

// One LIF timestep, 12-cycle critical path:
//   u = fma(v, 0.5, x); um = u - 0.5 (parallel with setp); v = sp ? um : u.
__device__ __forceinline__ void lif_step(float& v, float x, float& s_out) {
    float u  = fmaf(v, 0.5f, x);
    float um = u - 0.5f;
    bool  sp = u > 0.5f;
    s_out = sp ? 1.0f : 0.0f;   // off critical path
    v     = sp ? um : u;        // FSEL, pred-as-data
}

__global__ __launch_bounds__(ROWS_CTA, 1) void lif_kernel(const float4* __restrict__ x,
                                                          float4* __restrict__ out,
                                                          int ntiles) {
    extern __shared__ float4 smem[];              // [3 * TILE_V4]
    float4* bA = smem;                            // ring: cur, next, spare
    float4* bB = smem + TILE_V4;
    float4* bC = smem + 2 * TILE_V4;

    const int tid    = threadIdx.x;
    const int stride = gridDim.x;

    int tile0 = blockIdx.x;
    if (tile0 >= ntiles) return;

    // Prologue: prefetch first tile into bA.
    {
        const float4* src = x + (long long)tile0 * TILE_V4;
        #pragma unroll
        for (int i = 0; i < T_VEC; ++i)
            cp_async16(&bA[tid + ROWS_CTA * i], &src[tid + ROWS_CTA * i]);
        cp_commit();
    }

    for (long long tile = tile0; tile < ntiles; tile += stride) {
        float4* cur = bA;
        float4* nxt = bB;

        long long next = tile + stride;
        if (next < ntiles) {
            // nxt's bulk store was issued 2 iterations ago. Outstanding stores
            // now: {iter-2 (on nxt), iter-1}. wait<1> drains iter-2, leaves
            // iter-1 in flight -> safe to overwrite nxt, store stays async.
            if (tid == 0) bulk_wait<1>();
            __syncthreads();

            // ISSUE next tile's load BEFORE waiting on the current one: the
            // read stream stays non-empty while we stall. (r12 lesson.)
            const float4* src = x + next * TILE_V4;
            #pragma unroll
            for (int i = 0; i < T_VEC; ++i)
                cp_async16(&nxt[tid + ROWS_CTA * i], &src[tid + ROWS_CTA * i]);
            cp_commit();
            cp_wait<1>();       // current tile's load group has landed
        } else {
            cp_wait<0>();
        }
        __syncthreads();

        // ---- Compute: serial LIF scan of this thread's row, in place ----
        float v = 0.0f;
        float4* __restrict__ row = cur + tid * T_VEC;

        #pragma unroll
        for (int i = 0; i < T_VEC; ++i) {
            float4 xi = row[i];
            float4 so;
            lif_step(v, xi.x, so.x);
            lif_step(v, xi.y, so.y);
            lif_step(v, xi.z, so.z);
            lif_step(v, xi.w, so.w);
            row[i] = so;
        }

        // Order generic smem writes before the async-proxy bulk read, then
        // fire-and-forget the 50 KB tile store.
        fence_async_proxy();
        __syncthreads();
        if (tid == 0) {
            bulk_store(out + tile * TILE_V4, cur, TILE_BYTES);
            bulk_commit();
        }

        // Rotate ring: A<-B (next tile's data), B<-C (free), C<-A (storing).
        float4* t = bA; bA = bB; bB = bC; bC = t;
    }

    // Drain outstanding bulk stores before exit.
    if (tid == 0) bulk_wait<0>();
}

extern "C" void kernel_launch(void* const* d_in, const int* in_sizes, int n_in,
                              void* d_out, int out_size) {
    const float4* x = (const float4*)d_in[0];
    float4* out = (float4*)d_out;

    int n_rows = in_sizes[0] / T_STEPS;          // 524288
    int ntiles = n_rows / ROWS_CTA;              // 4096

    size_t smem_bytes = 3 * (size_t)TILE_V4 * sizeof(float4);   // 150 KB
    static bool attr_set = false;
    if (!attr_set) {
        cudaFuncSetAttribute(lif_kernel, cudaFuncAttributeMaxDynamicSharedMemorySize,
                             (int)smem_bytes);
        attr_set = true;
    }
    int grid = ntiles < GRID_P ? ntiles : GRID_P;
    lif_kernel<<<grid, ROWS_CTA, smem_bytes>>>(x, out, ntiles);
}